// round 4
// baseline (speedup 1.0000x reference)
#include <cuda_runtime.h>

// Kalman predict: x_hat = Ap x ; P_hat = Ap P Ap^T + Q,  Ap = triu(relu(A))
// 8 threads per batch: thread r owns row r of P. All global accesses are
// warp-coalesced (contiguous 32B per lane). Stage 1 (Ap*P) uses shuffle
// broadcasts within the 8-lane group; stage 2 (*Ap^T) is row-local.

__global__ void __launch_bounds__(256)
kf_predict_kernel(const float* __restrict__ x,
                  const float* __restrict__ P,
                  const float* __restrict__ A,
                  const float* __restrict__ sigma_p,
                  const float* __restrict__ sigma_v,
                  float* __restrict__ x_hat,
                  float* __restrict__ P_hat,
                  int B)
{
    const int tid  = blockIdx.x * blockDim.x + threadIdx.x;
    const int b    = tid >> 3;      // batch index
    const int r    = tid & 7;       // row within batch
    const bool valid = (b < B);
    const int bb   = valid ? b : (B - 1);   // clamped for safe loads; stores predicated
    const int lane = threadIdx.x & 31;
    const int gbase = lane & ~7;    // base lane of this 8-thread group

    // ---- full Ap = triu(relu(A)) with compile-time indices (36 live regs,
    //      strict-lower entries fold to 0) — needed for stage 2 column access ----
    float ap[8][8];
#pragma unroll
    for (int i = 0; i < 8; i++) {
#pragma unroll
        for (int j = 0; j < 8; j++) {
            ap[i][j] = (j >= i) ? fmaxf(__ldg(&A[i * 8 + j]), 0.0f) : 0.0f;
        }
    }

    // ---- this thread's own Ap row r (runtime r -> load from gmem, L1-hit;
    //      avoids dynamic register indexing) ----
    float apr[8];
#pragma unroll
    for (int j = 0; j < 8; j++) {
        float v = __ldg(&A[r * 8 + j]);
        apr[j] = (j >= r) ? fmaxf(v, 0.0f) : 0.0f;
    }

    const float sp = __ldg(sigma_p);
    const float sv = __ldg(sigma_v);

    // ---- x: one scalar per thread, fully coalesced ----
    const float xr = __ldg(&x[(size_t)bb * 8 + r]);

    // broadcast all 8 x values within the group
    float xj[8];
#pragma unroll
    for (int j = 0; j < 8; j++)
        xj[j] = __shfl_sync(0xffffffffu, xr, gbase + j);

    // ---- x_hat[r] = sum_j apr[j] * x[j]  (apr[j]=0 for j<r) ----
    {
        float s = 0.0f;
#pragma unroll
        for (int j = 0; j < 8; j++) s = fmaf(apr[j], xj[j], s);
        if (valid) x_hat[(size_t)b * 8 + r] = s;
    }

    // ---- load P row r: 2x float4, warp-contiguous ----
    float p[8];
    {
        const float4* p4 = reinterpret_cast<const float4*>(P + (size_t)bb * 64 + r * 8);
        float4 lo = __ldg(p4 + 0);
        float4 hi = __ldg(p4 + 1);
        p[0] = lo.x; p[1] = lo.y; p[2] = lo.z; p[3] = lo.w;
        p[4] = hi.x; p[5] = hi.y; p[6] = hi.z; p[7] = hi.w;
    }

    // ---- stage 1: t[k] = (Ap * P)[r][k] = sum_j apr[j] * P[j][k]
    //      P row j lives in lane gbase+j -> shuffle broadcast ----
    float t[8];
#pragma unroll
    for (int k = 0; k < 8; k++) t[k] = 0.0f;
#pragma unroll
    for (int j = 0; j < 8; j++) {
        const float a = apr[j];   // 0 when j < r
#pragma unroll
        for (int k = 0; k < 8; k++) {
            float pjk = __shfl_sync(0xffffffffu, p[k], gbase + j);
            t[k] = fmaf(a, pjk, t[k]);
        }
    }

    // ---- stage 2: o[l] = (t * Ap^T)[l] = sum_{k>=l} t[k] * ap[l][k] ----
    float o[8];
#pragma unroll
    for (int l = 0; l < 8; l++) {
        float s = 0.0f;
#pragma unroll
        for (int k = 0; k < 8; k++) {
            if (k >= l) s = fmaf(t[k], ap[l][k], s);
        }
        o[l] = s;
    }

    // ---- Q diagonal: d[r] = ((r odd)? w : h) * ((r<4)? sp : sv), add d^2 at col r ----
    {
        const float h = xj[2];
        const float w = xj[3];
        const float base_hw = (r & 1) ? w : h;
        const float sig = (r < 4) ? sp : sv;
        const float d = base_hw * sig;
        const float dd = d * d;
#pragma unroll
        for (int l = 0; l < 8; l++) {
            if (l == r) o[l] += dd;   // predicated, no dynamic indexing
        }
    }

    // ---- store P_hat row r: 2x float4, warp-contiguous ----
    if (valid) {
        float4* o4 = reinterpret_cast<float4*>(P_hat + (size_t)b * 64 + r * 8);
        o4[0] = make_float4(o[0], o[1], o[2], o[3]);
        o4[1] = make_float4(o[4], o[5], o[6], o[7]);
    }
}

extern "C" void kernel_launch(void* const* d_in, const int* in_sizes, int n_in,
                              void* d_out, int out_size)
{
    const float* x  = (const float*)d_in[0];   // (B, 8, 1)
    const float* P  = (const float*)d_in[1];   // (B, 8, 8)
    const float* A  = (const float*)d_in[2];   // (8, 8)
    const float* sp = (const float*)d_in[3];   // scalar
    const float* sv = (const float*)d_in[4];   // scalar

    const int B = in_sizes[0] / 8;

    float* out   = (float*)d_out;
    float* x_hat = out;                        // B*8 floats
    float* P_hat = out + (size_t)B * 8;        // B*64 floats

    const int threads = 256;
    const long long total = (long long)B * 8;
    const int blocks = (int)((total + threads - 1) / threads);
    kf_predict_kernel<<<blocks, threads>>>(x, P, A, sp, sv, x_hat, P_hat, B);
}

// round 5
// speedup vs baseline: 1.5536x; 1.5536x over previous
#include <cuda_runtime.h>

// Kalman predict: x_hat = Ap x ; P_hat = Ap P Ap^T + Q,  Ap = triu(relu(A))
// 1 thread per batch (all indices compile-time, no shuffles).
// Per-warp smem staging keeps every global access coalesced while the
// compute reads/writes its own batch row from padded smem (conflict-free).

#define BLOCK   160
#define WARPS   (BLOCK / 32)
#define BPW     32                 // batches per warp
#define STRIDE  68                 // padded floats per batch row (64 + 4)

__global__ void __launch_bounds__(BLOCK)
kf_predict_kernel(const float* __restrict__ x,
                  const float* __restrict__ P,
                  const float* __restrict__ A,
                  const float* __restrict__ sigma_p,
                  const float* __restrict__ sigma_v,
                  float* __restrict__ x_hat,
                  float* __restrict__ P_hat,
                  int B)
{
    __shared__ float sbuf[WARPS][BPW * STRIDE];   // 5 * 8704 B = 43520 B

    const int w = threadIdx.x >> 5;
    const int t = threadIdx.x & 31;
    const int warpBatch0 = (blockIdx.x * WARPS + w) * BPW;
    const int b = warpBatch0 + t;                 // this thread's batch
    const bool valid = (b < B);

    float* sb = sbuf[w];

    // ---- Ap = triu(relu(A)) : 16 uniform float4 loads, 1 wavefront each ----
    float ap[8][8];
    {
        const float4* A4 = reinterpret_cast<const float4*>(A);
#pragma unroll
        for (int i = 0; i < 8; i++) {
            float4 lo = __ldg(A4 + i * 2);
            float4 hi = __ldg(A4 + i * 2 + 1);
            float row[8] = {lo.x, lo.y, lo.z, lo.w, hi.x, hi.y, hi.z, hi.w};
#pragma unroll
            for (int j = 0; j < 8; j++)
                ap[i][j] = (j >= i) ? fmaxf(row[j], 0.0f) : 0.0f;
        }
    }
    const float sp = __ldg(sigma_p);
    const float sv = __ldg(sigma_v);

    // ---- stage this warp's 32 batches of P into smem, fully coalesced ----
    {
        const float4* src = reinterpret_cast<const float4*>(P) + (size_t)warpBatch0 * 16;
        const long long lim4 = ((long long)B * 64) / 4 - (long long)warpBatch0 * 16;
#pragma unroll
        for (int k = 0; k < 16; k++) {
            int g4 = t + 32 * k;                  // float4 idx in warp tile (0..511)
            int g4c = (g4 < lim4) ? g4 : 0;       // clamp (dead for full warps)
            int batch = g4c >> 4;
            int col   = (g4c & 15) << 2;
            float4 v = __ldg(src + g4c);
            *reinterpret_cast<float4*>(&sb[batch * STRIDE + col]) = v;
        }
    }
    __syncwarp();

    // ---- read own batch row from smem (conflict-free with STRIDE=68) ----
    float p[8][8];
#pragma unroll
    for (int r = 0; r < 8; r++) {
        float4 lo = *reinterpret_cast<const float4*>(&sb[t * STRIDE + r * 8]);
        float4 hi = *reinterpret_cast<const float4*>(&sb[t * STRIDE + r * 8 + 4]);
        p[r][0] = lo.x; p[r][1] = lo.y; p[r][2] = lo.z; p[r][3] = lo.w;
        p[r][4] = hi.x; p[r][5] = hi.y; p[r][6] = hi.z; p[r][7] = hi.w;
    }

    // ---- x: direct per-thread load (small traffic) ----
    float xv[8];
    {
        const int xb = valid ? b : 0;
        const float4* x4 = reinterpret_cast<const float4*>(x + (size_t)xb * 8);
        float4 a0 = __ldg(x4 + 0);
        float4 a1 = __ldg(x4 + 1);
        xv[0] = a0.x; xv[1] = a0.y; xv[2] = a0.z; xv[3] = a0.w;
        xv[4] = a1.x; xv[5] = a1.y; xv[6] = a1.z; xv[7] = a1.w;
    }

    // ---- x_hat = Ap x ----
    if (valid) {
        float xh[8];
#pragma unroll
        for (int i = 0; i < 8; i++) {
            float s = 0.0f;
#pragma unroll
            for (int j = 0; j < 8; j++)
                if (j >= i) s = fmaf(ap[i][j], xv[j], s);
            xh[i] = s;
        }
        float4* o4 = reinterpret_cast<float4*>(x_hat + (size_t)b * 8);
        o4[0] = make_float4(xh[0], xh[1], xh[2], xh[3]);
        o4[1] = make_float4(xh[4], xh[5], xh[6], xh[7]);
    }

    // ---- stage 2 first (row-local): p[j] <- v_j, v_j[l] = sum_k p[j][k]*ap[l][k] ----
#pragma unroll
    for (int j = 0; j < 8; j++) {
        float vrow[8];
#pragma unroll
        for (int l = 0; l < 8; l++) {
            float s = 0.0f;
#pragma unroll
            for (int k = 0; k < 8; k++)
                if (k >= l) s = fmaf(p[j][k], ap[l][k], s);
            vrow[l] = s;
        }
#pragma unroll
        for (int l = 0; l < 8; l++) p[j][l] = vrow[l];
    }

    // ---- Q diagonal terms ----
    const float h = xv[2];
    const float wd = xv[3];
    float dq[8];
    dq[0] = h * sp;  dq[1] = wd * sp;  dq[2] = h * sp;  dq[3] = wd * sp;
    dq[4] = h * sv;  dq[5] = wd * sv;  dq[6] = h * sv;  dq[7] = wd * sv;

    // ---- stage 1: o[i][l] = sum_{j>=i} ap[i][j] * v_j[l] ; write rows to smem ----
#pragma unroll
    for (int i = 0; i < 8; i++) {
        float orow[8];
#pragma unroll
        for (int l = 0; l < 8; l++) {
            float s = 0.0f;
#pragma unroll
            for (int j = 0; j < 8; j++)
                if (j >= i) s = fmaf(ap[i][j], p[j][l], s);
            orow[l] = s;
        }
        orow[i] = fmaf(dq[i], dq[i], orow[i]);
        *reinterpret_cast<float4*>(&sb[t * STRIDE + i * 8]) =
            make_float4(orow[0], orow[1], orow[2], orow[3]);
        *reinterpret_cast<float4*>(&sb[t * STRIDE + i * 8 + 4]) =
            make_float4(orow[4], orow[5], orow[6], orow[7]);
    }
    __syncwarp();

    // ---- coalesced store of the warp tile to P_hat ----
    {
        float4* dst = reinterpret_cast<float4*>(P_hat) + (size_t)warpBatch0 * 16;
        const long long lim4 = ((long long)B * 64) / 4 - (long long)warpBatch0 * 16;
#pragma unroll
        for (int k = 0; k < 16; k++) {
            int g4 = t + 32 * k;
            if (g4 < lim4) {
                int batch = g4 >> 4;
                int col   = (g4 & 15) << 2;
                dst[g4] = *reinterpret_cast<const float4*>(&sb[batch * STRIDE + col]);
            }
        }
    }
}

extern "C" void kernel_launch(void* const* d_in, const int* in_sizes, int n_in,
                              void* d_out, int out_size)
{
    const float* x  = (const float*)d_in[0];   // (B, 8, 1)
    const float* P  = (const float*)d_in[1];   // (B, 8, 8)
    const float* A  = (const float*)d_in[2];   // (8, 8)
    const float* sp = (const float*)d_in[3];   // scalar
    const float* sv = (const float*)d_in[4];   // scalar

    const int B = in_sizes[0] / 8;

    float* out   = (float*)d_out;
    float* x_hat = out;                        // B*8 floats
    float* P_hat = out + (size_t)B * 8;        // B*64 floats

    const int batchesPerBlock = WARPS * BPW;   // 160
    const int blocks = (B + batchesPerBlock - 1) / batchesPerBlock;
    kf_predict_kernel<<<blocks, BLOCK>>>(x, P, A, sp, sv, x_hat, P_hat, B);
}